// round 3
// baseline (speedup 1.0000x reference)
#include <cuda_runtime.h>
#include <math.h>

// Problem constants
#define BB 4
#define CC 256
#define HH 64
#define WW 64
#define HW 4096          // 64*64
#define HW4 1024         // HW/4
#define CR 16            // C/16 hidden
#define C8 32            // C/8

// ---------------- scratch (static device globals; no runtime alloc) ----------
__device__ float g_avg[BB * CC];
__device__ float g_max[BB * CC];
__device__ float g_chatt[BB * CC];
__device__ float g_avgs[BB * HW];
__device__ float g_maxs[BB * HW];
__device__ float g_sig[BB * HW];
// fallback scratch (only touched if gamma != 0, which setup_inputs never produces)
__device__ float g_q[BB * C8 * HW];
__device__ float g_k[BB * C8 * HW];
__device__ float g_v[BB * CC * HW];

// ---------------- Kernel A: per-(b,c) global avg + max pool ------------------
// grid = 1024 blocks (one per (b,c)), 256 threads; each thread 4 float4 loads.
__global__ void sca_pool_bc(const float* __restrict__ x) {
    int bc = blockIdx.x;                       // 0..1023
    const float4* p = (const float4*)(x + (size_t)bc * HW);
    float s = 0.f, m = -INFINITY;
#pragma unroll
    for (int i = 0; i < 4; ++i) {
        float4 v = p[threadIdx.x + i * 256];
        s += (v.x + v.y) + (v.z + v.w);
        m = fmaxf(m, fmaxf(fmaxf(v.x, v.y), fmaxf(v.z, v.w)));
    }
    __shared__ float ss[256], sm[256];
    ss[threadIdx.x] = s; sm[threadIdx.x] = m;
    __syncthreads();
    for (int off = 128; off > 0; off >>= 1) {
        if (threadIdx.x < off) {
            ss[threadIdx.x] += ss[threadIdx.x + off];
            sm[threadIdx.x] = fmaxf(sm[threadIdx.x], sm[threadIdx.x + off]);
        }
        __syncthreads();
    }
    if (threadIdx.x == 0) {
        g_avg[bc] = ss[0] * (1.f / (float)HW);
        g_max[bc] = sm[0];
    }
}

// ---------------- Kernel B: channel MLP + sigmoid ----------------------------
__global__ void sca_mlp(const float* __restrict__ w1, const float* __restrict__ w2) {
    int bb = blockIdx.x;
    int t = threadIdx.x;
    __shared__ float a[CC], mm[CC], h[2 * CR];
    a[t]  = g_avg[bb * CC + t];
    mm[t] = g_max[bb * CC + t];
    __syncthreads();
    if (t < 2 * CR) {
        const float* v = (t < CR) ? a : mm;
        int j = t & (CR - 1);
        float s = 0.f;
#pragma unroll 8
        for (int c = 0; c < CC; ++c) s += v[c] * w1[j * CC + c];
        h[t] = fmaxf(s, 0.f);
    }
    __syncthreads();
    float s = 0.f;
#pragma unroll
    for (int j = 0; j < CR; ++j) s += w2[t * CR + j] * (h[j] + h[CR + j]);
    g_chatt[bb * CC + t] = 1.f / (1.f + __expf(-s));
}

// ---------------- Kernel C: per-pixel channel mean/max of x*ch_att -----------
// grid = 256 blocks (4 batches x 64 pixel tiles of 64 px), blockDim (16,8).
// Thread (tx,ty): 4 consecutive pixels (float4) at tile*64 + tx*4, channels
// [ty*32, ty*32+32) fully unrolled (32 independent float4 loads).
__global__ void sca_spstats(const float* __restrict__ x) {
    int bb   = blockIdx.x >> 6;
    int tile = blockIdx.x & 63;
    int tx = threadIdx.x, ty = threadIdx.y;
    int p4 = tile * 16 + tx;                  // float4 index within image
    __shared__ float ch[CC];
    int tid = ty * 16 + tx;                   // 0..127
    ch[tid * 2]     = g_chatt[bb * CC + tid * 2];
    ch[tid * 2 + 1] = g_chatt[bb * CC + tid * 2 + 1];
    __syncthreads();
    const float4* xb = (const float4*)x + (size_t)bb * CC * HW4 + p4;
    float4 s = make_float4(0.f, 0.f, 0.f, 0.f);
    float4 m = make_float4(-INFINITY, -INFINITY, -INFINITY, -INFINITY);
    int c0 = ty * 32;
#pragma unroll
    for (int cc = 0; cc < 32; ++cc) {
        int c = c0 + cc;
        float4 v = xb[(size_t)c * HW4];
        float sc = ch[c];
        v.x *= sc; v.y *= sc; v.z *= sc; v.w *= sc;
        s.x += v.x; s.y += v.y; s.z += v.z; s.w += v.w;
        m.x = fmaxf(m.x, v.x); m.y = fmaxf(m.y, v.y);
        m.z = fmaxf(m.z, v.z); m.w = fmaxf(m.w, v.w);
    }
    __shared__ float4 ps[8][16], pm[8][16];
    ps[ty][tx] = s; pm[ty][tx] = m;
    __syncthreads();
    if (ty == 0) {
        float4 st = ps[0][tx], mt = pm[0][tx];
#pragma unroll
        for (int j = 1; j < 8; ++j) {
            float4 a = ps[j][tx], b = pm[j][tx];
            st.x += a.x; st.y += a.y; st.z += a.z; st.w += a.w;
            mt.x = fmaxf(mt.x, b.x); mt.y = fmaxf(mt.y, b.y);
            mt.z = fmaxf(mt.z, b.z); mt.w = fmaxf(mt.w, b.w);
        }
        const float inv = 1.f / (float)CC;
        st.x *= inv; st.y *= inv; st.z *= inv; st.w *= inv;
        ((float4*)g_avgs)[bb * HW4 + p4] = st;
        ((float4*)g_maxs)[bb * HW4 + p4] = mt;
    }
}

// ---------------- Kernel D: 7x7 conv(2->1) + sigmoid -> g_sig ----------------
// grid = 128, block = 128; one pixel per thread. Inputs are 128KB, L2-resident.
__global__ void sca_sig(const float* __restrict__ wsp) {
    __shared__ float wk[98];
    if (threadIdx.x < 98) wk[threadIdx.x] = wsp[threadIdx.x];
    __syncthreads();
    int p = blockIdx.x * 128 + threadIdx.x;   // 0..16383
    int bb = p >> 12;
    int pix = p & 4095;
    int py = pix >> 6, px = pix & 63;
    const float* as = g_avgs + bb * HW;
    const float* ms = g_maxs + bb * HW;
    float acc = 0.f;
#pragma unroll
    for (int ky = 0; ky < 7; ++ky) {
        int iy = py + ky - 3;
        if (iy < 0 || iy >= HH) continue;
#pragma unroll
        for (int kx = 0; kx < 7; ++kx) {
            int ix = px + kx - 3;
            if (ix < 0 || ix >= WW) continue;
            int p2 = iy * WW + ix;
            acc += wk[ky * 7 + kx] * as[p2] + wk[49 + ky * 7 + kx] * ms[p2];
        }
    }
    g_sig[p] = 1.f / (1.f + __expf(-acc));
}

// ---------------- Kernel E: pure streaming scale ------------------------------
// out[i] = x[i] * ch_att[b,c] * sig[b,pix]. 1M float4 elements.
// grid = 1024, block = 256, 4 independent float4 per thread.
__global__ void sca_scale(const float4* __restrict__ x, float4* __restrict__ out) {
    int base = blockIdx.x * 256 + threadIdx.x;   // 0..262143
#pragma unroll
    for (int u = 0; u < 4; ++u) {
        int i = base + u * 262144;               // 0..1048575
        int p4 = i & (HW4 - 1);
        int c  = (i >> 10) & (CC - 1);
        int bb = i >> 18;
        float sc = g_chatt[bb * CC + c];
        float4 sg = ((const float4*)g_sig)[bb * HW4 + p4];
        float4 v = x[i];
        v.x *= sc * sg.x; v.y *= sc * sg.y; v.z *= sc * sg.z; v.w *= sc * sg.w;
        out[i] = v;
    }
}

// ---------------- Guarded fallback: non-local attention (gamma != 0 only) ----
__global__ void sca_qkv(const float* __restrict__ gamma, const float* __restrict__ xcb,
                        const float* __restrict__ wq, const float* __restrict__ bq,
                        const float* __restrict__ wk_, const float* __restrict__ bk,
                        const float* __restrict__ wv, const float* __restrict__ bv) {
    if (*gamma == 0.f) return;
    int nth = gridDim.x * blockDim.x;
    int gt = blockIdx.x * blockDim.x + threadIdx.x;
    for (int idx = gt; idx < BB * C8 * HW; idx += nth) {
        int bb = idx / (C8 * HW);
        int r  = idx % (C8 * HW);
        int o = r / HW, pix = r % HW;
        float sq = bq[o], sk = bk[o];
        for (int c = 0; c < CC; ++c) {
            float xv = xcb[((size_t)bb * CC + c) * HW + pix];
            sq += wq[o * CC + c] * xv;
            sk += wk_[o * CC + c] * xv;
        }
        g_q[idx] = sq; g_k[idx] = sk;
    }
    for (int idx = gt; idx < BB * CC * HW; idx += nth) {
        int bb = idx / (CC * HW);
        int r  = idx % (CC * HW);
        int o = r / HW, pix = r % HW;
        float sv = bv[o];
        for (int c = 0; c < CC; ++c)
            sv += wv[o * CC + c] * xcb[((size_t)bb * CC + c) * HW + pix];
        g_v[idx] = sv;
    }
}

__global__ void sca_attn(const float* __restrict__ gamma, float* __restrict__ out) {
    float g = *gamma;
    if (g == 0.f) return;
    __shared__ float logits[HW];
    __shared__ float red[256];
    __shared__ float qi[C8];
    for (int row = blockIdx.x; row < BB * HW; row += gridDim.x) {
        int bb = row / HW, i = row % HW;
        if (threadIdx.x < C8) qi[threadIdx.x] = g_q[(bb * C8 + threadIdx.x) * HW + i];
        __syncthreads();
        float lm = -INFINITY;
        for (int j = threadIdx.x; j < HW; j += blockDim.x) {
            float s = 0.f;
            for (int d = 0; d < C8; ++d) s += qi[d] * g_k[(bb * C8 + d) * HW + j];
            logits[j] = s; lm = fmaxf(lm, s);
        }
        red[threadIdx.x] = lm; __syncthreads();
        for (int off = 128; off > 0; off >>= 1) {
            if (threadIdx.x < off) red[threadIdx.x] = fmaxf(red[threadIdx.x], red[threadIdx.x + off]);
            __syncthreads();
        }
        float mx = red[0];
        __syncthreads();
        float ls = 0.f;
        for (int j = threadIdx.x; j < HW; j += blockDim.x) {
            float e = expf(logits[j] - mx);
            logits[j] = e; ls += e;
        }
        red[threadIdx.x] = ls; __syncthreads();
        for (int off = 128; off > 0; off >>= 1) {
            if (threadIdx.x < off) red[threadIdx.x] += red[threadIdx.x + off];
            __syncthreads();
        }
        float inv = 1.f / red[0];
        __syncthreads();
        for (int c = threadIdx.x; c < CC; c += blockDim.x) {
            float s = 0.f;
            for (int j = 0; j < HW; ++j) s += g_v[((size_t)bb * CC + c) * HW + j] * logits[j];
            size_t oi = ((size_t)bb * CC + c) * HW + i;
            out[oi] = g * s * inv + out[oi];
        }
        __syncthreads();
    }
}

// ---------------- launch -----------------------------------------------------
extern "C" void kernel_launch(void* const* d_in, const int* in_sizes, int n_in,
                              void* d_out, int out_size) {
    const float* x     = (const float*)d_in[0];
    const float* w1    = (const float*)d_in[1];
    const float* w2    = (const float*)d_in[2];
    const float* w_sp  = (const float*)d_in[3];
    const float* wq    = (const float*)d_in[4];
    const float* bq    = (const float*)d_in[5];
    const float* wk    = (const float*)d_in[6];
    const float* bk    = (const float*)d_in[7];
    const float* wv    = (const float*)d_in[8];
    const float* bv    = (const float*)d_in[9];
    const float* gamma = (const float*)d_in[10];
    float* out = (float*)d_out;

    sca_pool_bc<<<BB * CC, 256>>>(x);
    sca_mlp<<<BB, 256>>>(w1, w2);
    sca_spstats<<<256, dim3(16, 8)>>>(x);
    sca_sig<<<128, 128>>>(w_sp);
    sca_scale<<<1024, 256>>>((const float4*)x, (float4*)out);
    // guarded fallback (no-ops when gamma == 0, which setup_inputs guarantees)
    sca_qkv<<<148, 256>>>(gamma, out, wq, bq, wk, bk, wv, bv);
    sca_attn<<<148, 256>>>(gamma, out);
}